// round 9
// baseline (speedup 1.0000x reference)
#include <cuda_runtime.h>
#include <cuda_fp8.h>
#include <cstdint>

// ---------------- geometry ----------------
#define T_DIM   4096
#define D_DIM   6144
#define NT0     3072
#define TDM     1024

// ---------------- tiling ------------------
#define KCH     128                  // fp8 K per chunk (128B row)
#define NZ      4                    // K splits
#define KSPLIT  (D_DIM/NZ)           // 1536 elems (=bytes)
#define NCHUNK  (KSPLIT/KCH)         // 12 chunks per K-quarter
#define NST     3                    // pipeline stages
#define TILE_B  16384                // 128 rows x 128 B
#define STAGE_B (2*TILE_B)           // A(shift) + B(base)
#define SMEM_DYN (NST*STAGE_B)       // 98304
#define NN0     24
#define NQQ     9
#define NTILE   (NN0*NQQ)            // 216

typedef unsigned int u32;

// ---------------- scratch (device globals) --------------
__device__ unsigned char g_x8[(size_t)T_DIM * D_DIM];    // 25 MB fp8 copy
__device__ float g_S2[T_DIM];
__device__ float g_diag[NZ * NTILE * 256];

// ---------------- PTX helpers ----------------
__device__ __forceinline__ u32 smem_u32(const void* p) {
    u32 a;
    asm("{ .reg .u64 t; cvta.to.shared.u64 t, %1; cvt.u32.u64 %0, t; }"
        : "=r"(a) : "l"(p));
    return a;
}
#define CP_COMMIT()  asm volatile("cp.async.commit_group;" ::: "memory")
#define CP_WAIT(n)   asm volatile("cp.async.wait_group %0;" :: "n"(n) : "memory")

#define LDSM4(r, addr) \
    asm volatile("ldmatrix.sync.aligned.m8n8.x4.shared.b16 {%0,%1,%2,%3}, [%4];" \
        : "=r"((r)[0]), "=r"((r)[1]), "=r"((r)[2]), "=r"((r)[3]) : "r"(addr))

#define MMAFP8(c, a, b0, b1) \
    asm volatile("mma.sync.aligned.m16n8k32.row.col.f32.e4m3.e4m3.f32 " \
        "{%0,%1,%2,%3}, {%4,%5,%6,%7}, {%8,%9}, {%0,%1,%2,%3};" \
        : "+f"((c)[0]), "+f"((c)[1]), "+f"((c)[2]), "+f"((c)[3]) \
        : "r"((a)[0]), "r"((a)[1]), "r"((a)[2]), "r"((a)[3]), "r"(b0), "r"(b1))

// ---------------------------------------------------------------------------
// Kernel 1: fp32 -> fp8 e4m3 convert + exact per-row sum of squares
// ---------------------------------------------------------------------------
__global__ void __launch_bounds__(256) s2cvt_kernel(const float* __restrict__ x) {
    int t = blockIdx.x;
    const float4* row = (const float4*)(x + (size_t)t * D_DIM);
    uint2* orow = (uint2*)(g_x8 + (size_t)t * D_DIM);
    float s = 0.f;
    for (int j = threadIdx.x; j < D_DIM / 8; j += 256) {
        float4 v0 = row[2 * j];
        float4 v1 = row[2 * j + 1];
        s += v0.x * v0.x + v0.y * v0.y + v0.z * v0.z + v0.w * v0.w;
        s += v1.x * v1.x + v1.y * v1.y + v1.z * v1.z + v1.w * v1.w;
        u32 q0 = __nv_cvt_float2_to_fp8x2(make_float2(v0.x, v0.y),
                                          __NV_SATFINITE, __NV_E4M3);
        u32 q1 = __nv_cvt_float2_to_fp8x2(make_float2(v0.z, v0.w),
                                          __NV_SATFINITE, __NV_E4M3);
        u32 q2 = __nv_cvt_float2_to_fp8x2(make_float2(v1.x, v1.y),
                                          __NV_SATFINITE, __NV_E4M3);
        u32 q3 = __nv_cvt_float2_to_fp8x2(make_float2(v1.z, v1.w),
                                          __NV_SATFINITE, __NV_E4M3);
        uint2 w;
        w.x = (q0 & 0xFFFFu) | (q1 << 16);
        w.y = (q2 & 0xFFFFu) | (q3 << 16);
        orow[j] = w;
    }
    __shared__ float red[256];
    red[threadIdx.x] = s;
    __syncthreads();
    for (int o = 128; o; o >>= 1) {
        if (threadIdx.x < o) red[threadIdx.x] += red[threadIdx.x + o];
        __syncthreads();
    }
    if (threadIdx.x == 0) g_S2[t] = red[0];
}

// ---------------------------------------------------------------------------
// Kernel 2: banded Gram matrix via mma.sync fp8 e4m3.
// CTA (n0, qq, z): tile G[r][c] = <x[(n0+qq)*128+r], x[n0*128+c]> over
// K-quarter z. 8 warps, each 64x32 output, register accumulators.
// ---------------------------------------------------------------------------
__device__ __forceinline__ void load_chunk(u32 stage, int kbase,
                                           int brow, int arow, int tid) {
    const unsigned char* xp = g_x8 + kbase;
#pragma unroll
    for (int it = 0; it < 8; it++) {
        int p = tid + it * 256;
        int t = p >> 10;                  // 0 = A (shift rows), 1 = B (base)
        int r = (p >> 3) & 127;
        int u = p & 7;                    // 16B unit within 128B row
        int grow = (t ? brow : arow) + r;
        const void* src = xp + (size_t)grow * D_DIM + (u << 4);
        u32 dst = stage + (t << 14) +
                  (((u32)(r * 128 + u * 16)) ^ (((u32)(r & 7)) << 4));
        asm volatile("cp.async.cg.shared.global [%0], [%1], 16;"
                     :: "r"(dst), "l"(src) : "memory");
    }
}

__global__ void __launch_bounds__(256, 2) corr_kernel() {
    extern __shared__ __align__(1024) char smem[];
    const u32 sb = smem_u32(smem);
    const int tid = threadIdx.x, l = tid & 31, wid = tid >> 5;
    const int warp_m = wid >> 2, warp_n = wid & 3;
    const int n0 = blockIdx.x, qq = blockIdx.y, z = blockIdx.z;
    const int brow = n0 << 7;
    const int arow = (n0 + qq) << 7;
    const int kbase = z * KSPLIT;         // bytes

    float c[4][4][4];
#pragma unroll
    for (int i = 0; i < 4; i++)
#pragma unroll
        for (int j = 0; j < 4; j++)
#pragma unroll
            for (int k = 0; k < 4; k++) c[i][j][k] = 0.f;

    // Unswizzled per-lane base offsets; swizzle XOR applied LAST at each
    // ldmatrix (swz depends only on row&7, invariant under all offsets).
    const int a_row = warp_m * 64 + ((l >> 3) & 1) * 8 + (l & 7);
    const u32 a_off = (u32)(a_row * 128 + (l >> 4) * 16);
    const u32 a_swz = ((u32)(a_row & 7)) << 4;
    const int b_row = warp_n * 32 + (l & 7);
    const u32 b_off = (u32)(b_row * 128 + (l >> 3) * 16);
    const u32 b_swz = ((u32)(b_row & 7)) << 4;

    // Prologue: 2 stages in flight
    for (int s = 0; s < 2; s++) {
        load_chunk(sb + s * STAGE_B, kbase + s * KCH, brow, arow, tid);
        CP_COMMIT();
    }

    int sidx = 0;
    for (int ch = 0; ch < NCHUNK; ch++) {
        CP_WAIT(1);
        __syncthreads();
        const u32 Ab = sb + sidx * STAGE_B + a_off;
        const u32 Bb = sb + sidx * STAGE_B + TILE_B + b_off;
#pragma unroll
        for (int kd = 0; kd < 2; kd++) {          // 64-byte k halves
            u32 bq[4][4];
#pragma unroll
            for (int ni = 0; ni < 4; ni++)
                LDSM4(bq[ni], (Bb + ni * 1024 + kd * 64) ^ b_swz);
#pragma unroll
            for (int h = 0; h < 2; h++) {         // 32-byte k steps
                u32 aq[4][4];
#pragma unroll
                for (int mi = 0; mi < 4; mi++)
                    LDSM4(aq[mi], (Ab + mi * 2048 + (kd * 2 + h) * 32) ^ a_swz);
#pragma unroll
                for (int mi = 0; mi < 4; mi++)
#pragma unroll
                    for (int ni = 0; ni < 4; ni++)
                        MMAFP8(c[mi][ni], aq[mi],
                               bq[ni][2 * h], bq[ni][2 * h + 1]);
            }
        }
        int cn = ch + 2;
        if (cn < NCHUNK) {
            int sn = sidx + 2; if (sn >= NST) sn -= NST;
            load_chunk(sb + sn * STAGE_B, kbase + cn * KCH, brow, arow, tid);
        }
        CP_COMMIT();
        if (++sidx == NST) sidx = 0;
    }

    // Epilogue: regs -> smem G (pitch 129) -> diagonal sums
    __syncthreads();
    float* G = (float*)smem;
#pragma unroll
    for (int mi = 0; mi < 4; mi++)
#pragma unroll
        for (int ni = 0; ni < 4; ni++) {
            int r0 = warp_m * 64 + mi * 16 + (l >> 2);
            int c0 = warp_n * 32 + ni * 8 + ((l & 3) << 1);
            G[r0 * 129 + c0]           = c[mi][ni][0];
            G[r0 * 129 + c0 + 1]       = c[mi][ni][1];
            G[(r0 + 8) * 129 + c0]     = c[mi][ni][2];
            G[(r0 + 8) * 129 + c0 + 1] = c[mi][ni][3];
        }
    __syncthreads();

    if (tid < 255) {
        int d = tid - 127;              // td = 128*qq + d
        float s = 0.f;
        for (int rr = 0; rr < 128; rr++) {
            int cc = rr - d;
            if ((unsigned)cc < 128u) s += G[rr * 129 + cc];
        }
        g_diag[((size_t)(z * NTILE + n0 * NQQ + qq)) * 256 + tid] = s;
    }
}

// ---------------------------------------------------------------------------
// Kernel 3: finalize. msd[td] = (A[td] + A[0] - 2*C[td]) / (NT0*D)
// ---------------------------------------------------------------------------
__global__ void __launch_bounds__(256) finalize_kernel(float* __restrict__ out) {
    const int td = blockIdx.x, tid = threadIdx.x;
    const int qq = td >> 7, d1 = td & 127;

    double c = 0.0;
    if (tid < NN0 * NZ) {
        int n = tid >> 2, zz = tid & 3;
        c = (double)g_diag[((size_t)(zz * NTILE + n * NQQ + qq)) * 256 + 127 + d1];
        if (d1)
            c += (double)g_diag[((size_t)(zz * NTILE + n * NQQ + qq + 1)) * 256 + d1 - 1];
    }

    double a = 0.0, a0 = 0.0;
    for (int j = tid; j < NT0; j += 256) {
        a  += (double)g_S2[td + j];
        a0 += (double)g_S2[j];
    }

    double part = a + a0 - 2.0 * c;
    __shared__ double red[256];
    red[tid] = part;
    __syncthreads();
    for (int o = 128; o; o >>= 1) {
        if (tid < o) red[tid] += red[tid + o];
        __syncthreads();
    }
    if (tid == 0) {
        const double invN = 1.0 / ((double)NT0 * (double)D_DIM);
        out[td] = (td == 0) ? 0.0f : (float)(red[0] * invN);
    }
}

// ---------------------------------------------------------------------------
extern "C" void kernel_launch(void* const* d_in, const int* in_sizes, int n_in,
                              void* d_out, int out_size) {
    (void)in_sizes; (void)n_in; (void)out_size;
    const float* x = (const float*)d_in[0];
    float* out = (float*)d_out;

    static bool attr_set = false;
    if (!attr_set) {
        cudaFuncSetAttribute(corr_kernel,
                             cudaFuncAttributeMaxDynamicSharedMemorySize,
                             SMEM_DYN);
        attr_set = true;
    }

    s2cvt_kernel<<<T_DIM, 256>>>(x);
    corr_kernel<<<dim3(NN0, NQQ, NZ), 256, SMEM_DYN>>>();
    finalize_kernel<<<TDM, 256>>>(out);
}